// round 8
// baseline (speedup 1.0000x reference)
#include <cuda_runtime.h>

#define TT   128
#define BB   256
#define SIG  64
#define MET  32
#define HH   256
#define FF   16
#define KTOT 352          // 256 (h) + 64 (signal) + 32 (metmast)
#define NG   1024         // 4 gates * 256 cols
#define NCTA 128
#define NTHR 256
#define BPC  2
#define APAD 36           // A tile: k-major, 32 r-values padded to 36 (float4-aligned)

// ---------------- scratch (static device allocations only) ----------------
__device__ __align__(16) float g_U[KTOT * NG];      // packed [U_i|U_ste|U_c|U_o ; W_sig ; W_met]
__device__ __align__(16) float g_bias[NG];
__device__ __align__(16) float g_Ufre[KTOT * FF];
__device__ __align__(16) float g_bfre[FF];
__device__ __align__(16) float g_trig[TT * 32];     // per step: 16 cos then 16 sin
__device__ __align__(16) float g_h[BB * HH];
__device__ __align__(16) float g_Z[BB * NG];
__device__ unsigned g_bar_count;
__device__ unsigned g_bar_gen;

// ---------------- helpers ----------------
__device__ __forceinline__ float hsig(float x) {
    return __saturatef(fmaf(x, 0.16666667f, 0.5f));
}
__device__ __forceinline__ unsigned long long pack2(float x, float y) {
    unsigned long long r;
    asm("mov.b64 %0, {%1, %2};" : "=l"(r) : "f"(x), "f"(y));
    return r;
}
__device__ __forceinline__ void fma2(unsigned long long &d, unsigned long long a, unsigned long long b) {
    asm("fma.rn.f32x2 %0, %1, %2, %0;" : "+l"(d) : "l"(a), "l"(b));
}
__device__ __forceinline__ void add2(unsigned long long &d, unsigned long long a) {
    asm("add.rn.f32x2 %0, %0, %1;" : "+l"(d) : "l"(a));
}

// Release/acquire grid barrier; all cross-CTA data moves through L2
// (__ldcg/__stcg), so no L1 invalidate needed -> L1 stays warm.
__device__ __forceinline__ void grid_barrier(unsigned gen) {
    __syncthreads();
    if (threadIdx.x == 0) {
        unsigned arr;
        asm volatile("atom.add.acq_rel.gpu.global.u32 %0, [%1], 1;"
                     : "=r"(arr) : "l"(&g_bar_count) : "memory");
        if (arr == NCTA - 1) {
            asm volatile("st.relaxed.gpu.global.u32 [%0], 0;"
                         :: "l"(&g_bar_count) : "memory");
            asm volatile("st.release.gpu.global.u32 [%0], %1;"
                         :: "l"(&g_bar_gen), "r"(gen) : "memory");
        } else {
            unsigned cur;
            do {
                asm volatile("ld.acquire.gpu.global.u32 %0, [%1];"
                             : "=r"(cur) : "l"(&g_bar_gen) : "memory");
            } while (cur < gen);
        }
    }
    __syncthreads();
}

// ---------------- pack kernel ----------------
__global__ void pack_kernel(
    const float* __restrict__ Wi_s,  const float* __restrict__ Wste_s, const float* __restrict__ Wfre_s,
    const float* __restrict__ Wc_s,  const float* __restrict__ Wo_s,
    const float* __restrict__ Wi_m,  const float* __restrict__ Wste_m, const float* __restrict__ Wfre_m,
    const float* __restrict__ Wc_m,  const float* __restrict__ Wo_m,
    const float* __restrict__ Ui,    const float* __restrict__ bi,
    const float* __restrict__ Uste,  const float* __restrict__ bste,
    const float* __restrict__ Ufre,  const float* __restrict__ bfre,
    const float* __restrict__ Uc,    const float* __restrict__ bc,
    const float* __restrict__ Uo,    const float* __restrict__ bo)
{
    int idx0   = blockIdx.x * blockDim.x + threadIdx.x;
    int stride = gridDim.x * blockDim.x;

    for (int idx = idx0; idx < KTOT * NG; idx += stride) {
        int k = idx / NG, c = idx % NG;
        int g = c >> 8, j = c & 255;
        const float* U4[4]  = {Ui, Uste, Uc, Uo};
        const float* Ws4[4] = {Wi_s, Wste_s, Wc_s, Wo_s};
        const float* Wm4[4] = {Wi_m, Wste_m, Wc_m, Wo_m};
        float v;
        if (k < HH)            v = U4[g][k * HH + j];
        else if (k < HH + SIG) v = Ws4[g][(k - HH) * HH + j];
        else                   v = Wm4[g][(k - HH - SIG) * HH + j];
        g_U[idx] = v;
    }
    for (int idx = idx0; idx < KTOT * FF; idx += stride) {
        int k = idx / FF, f = idx % FF;
        float v;
        if (k < HH)            v = Ufre[k * FF + f];
        else if (k < HH + SIG) v = Wfre_s[(k - HH) * FF + f];
        else                   v = Wfre_m[(k - HH - SIG) * FF + f];
        g_Ufre[idx] = v;
    }
    for (int idx = idx0; idx < NG; idx += stride) {
        int g = idx >> 8, j = idx & 255;
        const float* b4[4] = {bi, bste, bc, bo};
        g_bias[idx] = b4[g][j];
    }
    for (int idx = idx0; idx < FF; idx += stride) g_bfre[idx] = bfre[idx];
    for (int idx = idx0; idx < TT * FF; idx += stride) {
        int t = idx / FF, f = idx % FF;
        float om = 6.2831854820251465f * (float)(t + 1) * ((float)f / 16.0f);
        double omd = (double)om;
        g_trig[t * 32 + f]      = (float)cos(omd);
        g_trig[t * 32 + 16 + f] = (float)sin(omd);
    }
    if (idx0 == 0) { g_bar_count = 0; g_bar_gen = 0; }
}

// ---------------- persistent recurrent kernel ----------------
// SMEM layout (float offsets):
#define SM_US    0                          // 352*64  = 22528 (weight slice, persistent)
#define SM_UFRE  (SM_US   + KTOT * 64)      // 5632
#define SM_SRE   (SM_UFRE + KTOT * FF)      // 8192
#define SM_SIM   (SM_SRE  + BPC * FF * HH)  // 8192
#define SM_HS    (SM_SIM  + BPC * FF * HH)  // 512
#define SM_A     (SM_HS   + BPC * HH)       // A[k*APAD + r], k<352, r<32: 352*36 = 12672
#define SM_FRE   (SM_A    + KTOT * APAD)    // 32
#define SM_RED   (SM_FRE  + 32)             // 256
#define SM_TRIG  (SM_RED  + 256)            // 32
#define SM_TOTAL (SM_TRIG + 32)             // 58048 floats = 232192 B (<= 232448 cap)

__global__ void __launch_bounds__(NTHR, 1) sfm_kernel(
    const float* __restrict__ signal, const float* __restrict__ metmast,
    const float* __restrict__ Ua,     const float* __restrict__ ba,
    const float* __restrict__ Wp,     const float* __restrict__ bp,
    const float* __restrict__ fcw,    const float* __restrict__ fcb,
    float* __restrict__ out)
{
    extern __shared__ float sm[];
    float* U_s    = sm + SM_US;
    float* Ufre_s = sm + SM_UFRE;
    float* S_re   = sm + SM_SRE;
    float* S_im   = sm + SM_SIM;
    float* h_s    = sm + SM_HS;
    float* A      = sm + SM_A;
    float* fre_s  = sm + SM_FRE;
    float* red    = sm + SM_RED;
    float* trig_s = sm + SM_TRIG;

    const int tid   = threadIdx.x;
    const int ct    = blockIdx.x;
    const int bt    = ct & 7;            // 8 b-tiles of 32 rows
    const int ctile = ct >> 3;           // 16 c-tiles of 64 cols
    const int b0    = bt * 32;
    const int c0    = ctile * 64;

    // K-group split for the GEMM
    const int gid   = tid >> 7;          // 0 or 1: which K half
    const int gtid  = tid & 127;
    const int gty   = gtid >> 4;         // 0..7  -> rows gty*4 .. +4
    const int gtx   = gtid & 15;         // 0..15 -> cols gtx*4 .. +4
    const int kbase = gid * 176;

    // elementwise ownership: 2 rows inside this CTA's own b-tile
    const int lr0   = 2 * ctile;         // local rows lr0, lr0+1
    const int bown0 = b0 + lr0;

    // ---- persistent loads into smem ----
    for (int idx = tid; idx < KTOT * 64; idx += NTHR) {
        int k = idx >> 6, cc = idx & 63;
        U_s[idx] = g_U[k * NG + c0 + cc];
    }
    for (int idx = tid; idx < KTOT * FF; idx += NTHR) Ufre_s[idx] = g_Ufre[idx];

    // ---- state init ----
    for (int i = tid; i < BPC * FF * HH; i += NTHR) { S_re[i] = 0.f; S_im[i] = 0.f; }
    for (int i = tid; i < BPC * HH; i += NTHR) h_s[i] = 0.f;
#pragma unroll
    for (int lb = 0; lb < BPC; lb++) __stcg(&g_h[(bown0 + lb) * HH + tid], 0.f);

    float ba_r = ba[tid];
    float ua_r[FF];
#pragma unroll
    for (int f = 0; f < FF; f++) ua_r[f] = Ua[f];

    // bias for this thread's 4 output columns (group 0 only folds bias)
    unsigned long long binit0, binit1;
    {
        float4 bv = *(const float4*)&g_bias[c0 + gtx * 4];
        binit0 = pack2(bv.x, bv.y); binit1 = pack2(bv.z, bv.w);
    }

    unsigned gen = 0;
    grid_barrier(++gen);

    for (int t = 0; t < TT; t++) {
        // ========== stage full A tile: A[k*APAD + r], k in [0,352), r in [0,32) ==========
#pragma unroll 1
        for (int idx = tid; idx < 32 * KTOT; idx += NTHR) {
            int r = idx / KTOT;
            int k = idx - r * KTOT;
            int b = b0 + r;
            float v;
            if (k < HH)            v = __ldcg(&g_h[b * HH + k]);
            else if (k < HH + SIG) v = signal[(b * TT + t) * SIG + (k - HH)];
            else                   v = metmast[(b * TT + t) * MET + (k - HH - SIG)];
            A[k * APAD + r] = v;
        }
        if (tid < 32) trig_s[tid] = g_trig[t * 32 + tid];
        __syncthreads();

        // ========== GEMM: each K-group computes full 32x64 tile over half K ==========
        unsigned long long acc[8];
        if (gid == 0) {
            acc[0] = binit0; acc[1] = binit1; acc[2] = binit0; acc[3] = binit1;
            acc[4] = binit0; acc[5] = binit1; acc[6] = binit0; acc[7] = binit1;
        } else {
#pragma unroll
            for (int j = 0; j < 8; j++) acc[j] = 0ull;
        }
        {
            const float* Arow = &A[kbase * APAD + gty * 4];
            const float* Urow = &U_s[kbase * 64 + gtx * 4];
#pragma unroll 16
            for (int kk = 0; kk < 176; kk++) {
                float4 a4 = *(const float4*)(Arow + kk * APAD);
                ulonglong2 uu = *(const ulonglong2*)(Urow + kk * 64);
                unsigned long long h0 = pack2(a4.x, a4.x);
                unsigned long long h1 = pack2(a4.y, a4.y);
                unsigned long long h2 = pack2(a4.z, a4.z);
                unsigned long long h3 = pack2(a4.w, a4.w);
                fma2(acc[0], h0, uu.x); fma2(acc[1], h0, uu.y);
                fma2(acc[2], h1, uu.x); fma2(acc[3], h1, uu.y);
                fma2(acc[4], h2, uu.x); fma2(acc[5], h2, uu.y);
                fma2(acc[6], h3, uu.x); fma2(acc[7], h3, uu.y);
            }
        }
        __syncthreads();   // A reads (GEMM) done

        // ========== fre gate (reads staged A; must finish before A region is reused) ==========
#pragma unroll 1
        for (int lb = 0; lb < BPC; lb++) {
            int f = tid & 15, ch = tid >> 4;
            int lr = lr0 + lb;
            float s = 0.f;
            int k0 = ch * 22;   // 16 chunks * 22 = 352
#pragma unroll
            for (int q = 0; q < 22; q++) {
                int k = k0 + q;
                s = fmaf(A[k * APAD + lr], Ufre_s[k * FF + f], s);
            }
            red[tid] = s;
            __syncthreads();
            if (tid < FF) {
                float tot = g_bfre[tid];
#pragma unroll
                for (int j = 0; j < 16; j++) tot += red[tid + 16 * j];
                fre_s[lb * FF + tid] = hsig(tot);
            }
            __syncthreads();
        }

        // ========== cross-group reduction (partials reuse A region, 8192 <= 12672) ==========
        {
            unsigned long long* part = (unsigned long long*)(sm + SM_A);
            if (gid == 1) {
#pragma unroll
                for (int j = 0; j < 8; j++) part[j * 128 + gtid] = acc[j];
            }
            __syncthreads();
            if (gid == 0) {
#pragma unroll
                for (int j = 0; j < 8; j++) add2(acc[j], part[j * 128 + gtid]);
                // write Z tile to L2 (consumed by other CTAs)
#pragma unroll
                for (int r = 0; r < 4; r++) {
                    unsigned long long* p =
                        (unsigned long long*)&g_Z[(b0 + gty * 4 + r) * NG + c0 + gtx * 4];
                    asm volatile("st.global.cg.v2.u64 [%0], {%1, %2};"
                                 :: "l"(p), "l"(acc[r * 2]), "l"(acc[r * 2 + 1]) : "memory");
                }
            }
        }
        grid_barrier(++gen);

        // ========== elementwise phase (own 2 batches, state in smem) ==========
#pragma unroll 1
        for (int lb = 0; lb < BPC; lb++) {
            int b = bown0 + lb;
            const float* Zb = &g_Z[b * NG];
            float xi   = __ldcg(&Zb[tid]);
            float xste = __ldcg(&Zb[HH + tid]);
            float xc   = __ldcg(&Zb[2 * HH + tid]);
            float xo   = __ldcg(&Zb[3 * HH + tid]);
            float ig  = hsig(xi);
            float ste = hsig(xste);
            float cg  = ig * tanhf(xc);
            float og  = hsig(xo);
            float acc_a = 0.f;
#pragma unroll
            for (int f = 0; f < FF; f++) {
                float fm = ste * fre_s[lb * FF + f];
                int sidx = (lb * FF + f) * HH + tid;
                float sr = fmaf(fm, S_re[sidx], cg * trig_s[f]);
                float si = fmaf(fm, S_im[sidx], cg * trig_s[16 + f]);
                S_re[sidx] = sr; S_im[sidx] = si;
                acc_a = fmaf(fmaf(sr, sr, si * si), ua_r[f], acc_a);
            }
            float a  = tanhf(acc_a + ba_r);
            float hn = og * a;
            h_s[lb * HH + tid] = hn;
            __stcg(&g_h[b * HH + tid], hn);
        }
        grid_barrier(++gen);
    }

    // ========== output: out[b] = ((h.Wp + bp) * fcw + fcb) ==========
    for (int lb = 0; lb < BPC; lb++) {
        int b = bown0 + lb;
        red[tid] = h_s[lb * HH + tid] * Wp[tid];
        __syncthreads();
        for (int s = 128; s > 0; s >>= 1) {
            if (tid < s) red[tid] += red[tid + s];
            __syncthreads();
        }
        if (tid == 0) out[b] = fmaf(red[0] + bp[0], fcw[0], fcb[0]);
        __syncthreads();
    }
}

// ---------------- launch ----------------
extern "C" void kernel_launch(void* const* d_in, const int* in_sizes, int n_in,
                              void* d_out, int out_size) {
    const float* signal = (const float*)d_in[0];
    const float* metmast = (const float*)d_in[1];
    const float* Wi_s   = (const float*)d_in[2];
    const float* Wste_s = (const float*)d_in[3];
    const float* Wfre_s = (const float*)d_in[4];
    const float* Wc_s   = (const float*)d_in[5];
    const float* Wo_s   = (const float*)d_in[6];
    const float* Wi_m   = (const float*)d_in[7];
    const float* Wste_m = (const float*)d_in[8];
    const float* Wfre_m = (const float*)d_in[9];
    const float* Wc_m   = (const float*)d_in[10];
    const float* Wo_m   = (const float*)d_in[11];
    const float* Ui     = (const float*)d_in[12];
    const float* bi     = (const float*)d_in[13];
    const float* Uste   = (const float*)d_in[14];
    const float* bste   = (const float*)d_in[15];
    const float* Ufre   = (const float*)d_in[16];
    const float* bfre   = (const float*)d_in[17];
    const float* Uc     = (const float*)d_in[18];
    const float* bc     = (const float*)d_in[19];
    const float* Uo     = (const float*)d_in[20];
    const float* bo     = (const float*)d_in[21];
    const float* Ua     = (const float*)d_in[22];
    const float* ba     = (const float*)d_in[23];
    const float* Wp     = (const float*)d_in[24];
    const float* bp     = (const float*)d_in[25];
    const float* fcw    = (const float*)d_in[26];
    const float* fcb    = (const float*)d_in[27];
    float* out = (float*)d_out;

    static int smem_set = 0;
    const int SMEM_BYTES = SM_TOTAL * 4;   // 232192 B
    if (!smem_set) {
        cudaFuncSetAttribute(sfm_kernel, cudaFuncAttributeMaxDynamicSharedMemorySize, SMEM_BYTES);
        smem_set = 1;
    }

    pack_kernel<<<64, 256>>>(Wi_s, Wste_s, Wfre_s, Wc_s, Wo_s,
                             Wi_m, Wste_m, Wfre_m, Wc_m, Wo_m,
                             Ui, bi, Uste, bste, Ufre, bfre, Uc, bc, Uo, bo);
    sfm_kernel<<<NCTA, NTHR, SMEM_BYTES>>>(signal, metmast, Ua, ba, Wp, bp, fcw, fcb, out);
}

// round 9
// speedup vs baseline: 1.3567x; 1.3567x over previous
#include <cuda_runtime.h>

#define TT   128
#define BB   256
#define SIG  64
#define MET  32
#define HH   256
#define FF   16
#define KTOT 352          // 256 (h) + 64 (signal) + 32 (metmast)
#define NG   1024         // 4 gates * 256 cols
#define NCTA 128
#define NTHR 256
#define BPC  2
#define NGRP 16           // CTAs per barrier group (one b-tile)

// ---------------- scratch (static device allocations only) ----------------
__device__ __align__(16) float g_U[KTOT * NG];      // packed [U_i|U_ste|U_c|U_o ; W_sig ; W_met]
__device__ __align__(16) float g_bias[NG];
__device__ __align__(16) float g_Ufre[KTOT * FF];
__device__ __align__(16) float g_bfre[FF];
__device__ __align__(16) float g_trig[TT * 32];     // per step: 16 cos then 16 sin
__device__ __align__(16) float g_h[BB * HH];
__device__ __align__(16) float g_Z[BB * NG];
// 8 independent group barriers, 256-B stride (avoid L2 hash pair-collisions)
__device__ __align__(256) unsigned g_gbar[8 * 64];  // [grp*64+0]=count, [grp*64+1]=gen

// ---------------- helpers ----------------
__device__ __forceinline__ float hsig(float x) {
    return __saturatef(fmaf(x, 0.16666667f, 0.5f));
}
__device__ __forceinline__ unsigned long long pack2(float x, float y) {
    unsigned long long r;
    asm("mov.b64 %0, {%1, %2};" : "=l"(r) : "f"(x), "f"(y));
    return r;
}
__device__ __forceinline__ void fma2(unsigned long long &d, unsigned long long a, unsigned long long b) {
    asm("fma.rn.f32x2 %0, %1, %2, %0;" : "+l"(d) : "l"(a), "l"(b));
}

// 16-CTA group barrier, release/acquire through L2 only. All cross-CTA data
// moves via __ldcg/__stcg, so L1 never needs invalidation.
__device__ __forceinline__ void group_barrier(int grp, unsigned gen) {
    __syncthreads();
    if (threadIdx.x == 0) {
        unsigned* cnt = &g_gbar[grp * 64];
        unsigned* gv  = &g_gbar[grp * 64 + 1];
        unsigned arr;
        asm volatile("atom.add.acq_rel.gpu.global.u32 %0, [%1], 1;"
                     : "=r"(arr) : "l"(cnt) : "memory");
        if (arr == NGRP - 1) {
            asm volatile("st.relaxed.gpu.global.u32 [%0], 0;" :: "l"(cnt) : "memory");
            asm volatile("st.release.gpu.global.u32 [%0], %1;" :: "l"(gv), "r"(gen) : "memory");
        } else {
            unsigned cur;
            do {
                asm volatile("ld.acquire.gpu.global.u32 %0, [%1];"
                             : "=r"(cur) : "l"(gv) : "memory");
            } while (cur < gen);
        }
    }
    __syncthreads();
}

// ---------------- pack kernel ----------------
__global__ void pack_kernel(
    const float* __restrict__ Wi_s,  const float* __restrict__ Wste_s, const float* __restrict__ Wfre_s,
    const float* __restrict__ Wc_s,  const float* __restrict__ Wo_s,
    const float* __restrict__ Wi_m,  const float* __restrict__ Wste_m, const float* __restrict__ Wfre_m,
    const float* __restrict__ Wc_m,  const float* __restrict__ Wo_m,
    const float* __restrict__ Ui,    const float* __restrict__ bi,
    const float* __restrict__ Uste,  const float* __restrict__ bste,
    const float* __restrict__ Ufre,  const float* __restrict__ bfre,
    const float* __restrict__ Uc,    const float* __restrict__ bc,
    const float* __restrict__ Uo,    const float* __restrict__ bo)
{
    int idx0   = blockIdx.x * blockDim.x + threadIdx.x;
    int stride = gridDim.x * blockDim.x;

    for (int idx = idx0; idx < KTOT * NG; idx += stride) {
        int k = idx / NG, c = idx % NG;
        int g = c >> 8, j = c & 255;
        const float* U4[4]  = {Ui, Uste, Uc, Uo};
        const float* Ws4[4] = {Wi_s, Wste_s, Wc_s, Wo_s};
        const float* Wm4[4] = {Wi_m, Wste_m, Wc_m, Wo_m};
        float v;
        if (k < HH)            v = U4[g][k * HH + j];
        else if (k < HH + SIG) v = Ws4[g][(k - HH) * HH + j];
        else                   v = Wm4[g][(k - HH - SIG) * HH + j];
        g_U[idx] = v;
    }
    for (int idx = idx0; idx < KTOT * FF; idx += stride) {
        int k = idx / FF, f = idx % FF;
        float v;
        if (k < HH)            v = Ufre[k * FF + f];
        else if (k < HH + SIG) v = Wfre_s[(k - HH) * FF + f];
        else                   v = Wfre_m[(k - HH - SIG) * FF + f];
        g_Ufre[idx] = v;
    }
    for (int idx = idx0; idx < NG; idx += stride) {
        int g = idx >> 8, j = idx & 255;
        const float* b4[4] = {bi, bste, bc, bo};
        g_bias[idx] = b4[g][j];
    }
    for (int idx = idx0; idx < FF; idx += stride) g_bfre[idx] = bfre[idx];
    for (int idx = idx0; idx < TT * FF; idx += stride) {
        int t = idx / FF, f = idx % FF;
        float om = 6.2831854820251465f * (float)(t + 1) * ((float)f / 16.0f);
        double omd = (double)om;
        g_trig[t * 32 + f]      = (float)cos(omd);
        g_trig[t * 32 + 16 + f] = (float)sin(omd);
    }
    for (int idx = idx0; idx < 8 * 64; idx += stride) g_gbar[idx] = 0;
}

// ---------------- persistent recurrent kernel ----------------
// SMEM layout (float offsets):
#define SM_US    0                          // 352*64  = 22528 (weight slice, persistent)
#define SM_UFRE  (SM_US   + KTOT * 64)      // 5632
#define SM_SRE   (SM_UFRE + KTOT * FF)      // 8192
#define SM_SIM   (SM_SRE  + BPC * FF * HH)  // 8192
#define SM_HS    (SM_SIM  + BPC * FF * HH)  // 512
#define SM_A     (SM_HS   + BPC * HH)       // 2*32*34 = 2176 (double-buffered A tile)
#define SM_TRIG  (SM_A    + 2 * 32 * 34)    // 4096 (full trig table)
#define SM_XS    (SM_TRIG + TT * 32)        // 192
#define SM_FRE   (SM_XS   + BPC * 96)       // 32
#define SM_RED   (SM_FRE  + 32)             // 256
#define SM_TOTAL (SM_RED  + 256)            // 51872 floats = 207488 B

__global__ void __launch_bounds__(NTHR, 1) sfm_kernel(
    const float* __restrict__ signal, const float* __restrict__ metmast,
    const float* __restrict__ Ua,     const float* __restrict__ ba,
    const float* __restrict__ Wp,     const float* __restrict__ bp,
    const float* __restrict__ fcw,    const float* __restrict__ fcb,
    float* __restrict__ out)
{
    extern __shared__ float sm[];
    float* U_s    = sm + SM_US;
    float* Ufre_s = sm + SM_UFRE;
    float* S_re   = sm + SM_SRE;
    float* S_im   = sm + SM_SIM;
    float* h_s    = sm + SM_HS;
    float* hsA    = sm + SM_A;
    float* trig_a = sm + SM_TRIG;
    float* x_s    = sm + SM_XS;
    float* fre_s  = sm + SM_FRE;
    float* red    = sm + SM_RED;

    const int tid   = threadIdx.x;
    const int ct    = blockIdx.x;
    const int bt    = ct & 7;            // 8 b-tiles of 32 rows  == barrier group
    const int ctile = ct >> 3;           // 16 c-tiles of 64 cols == rank inside group
    const int b0    = bt * 32;
    const int c0    = ctile * 64;
    const int ty    = tid >> 4;          // rows ty*2, ty*2+1
    const int tx    = tid & 15;          // cols tx*4 .. +4

    // group-local elementwise ownership: 2 rows inside this CTA's own b-tile.
    // All producers/consumers of this CTA's data share bt -> group barrier only.
    const int lr0   = 2 * ctile;
    const int bown0 = b0 + lr0;

    // ---- persistent loads into smem ----
    for (int idx = tid; idx < KTOT * 64; idx += NTHR) {
        int k = idx >> 6, cc = idx & 63;
        U_s[idx] = g_U[k * NG + c0 + cc];
    }
    for (int idx = tid; idx < KTOT * FF; idx += NTHR) Ufre_s[idx] = g_Ufre[idx];
    for (int idx = tid; idx < TT * 32; idx += NTHR)   trig_a[idx] = g_trig[idx];

    // ---- state init ----
    for (int i = tid; i < BPC * FF * HH; i += NTHR) { S_re[i] = 0.f; S_im[i] = 0.f; }
    for (int i = tid; i < BPC * HH; i += NTHR) h_s[i] = 0.f;
#pragma unroll
    for (int lb = 0; lb < BPC; lb++) __stcg(&g_h[(bown0 + lb) * HH + tid], 0.f);

    float ba_r = ba[tid];
    float ua_r[FF];
#pragma unroll
    for (int f = 0; f < FF; f++) ua_r[f] = Ua[f];

    unsigned long long binit0, binit1;
    {
        float4 bv = *(const float4*)&g_bias[c0 + tx * 4];
        binit0 = pack2(bv.x, bv.y); binit1 = pack2(bv.z, bv.w);
    }

    unsigned gen = 0;
    group_barrier(bt, ++gen);

    for (int t = 0; t < TT; t++) {
        // ================= GEMM phase: Z = bias + [h|xs|xm] @ [U;W] =================
        unsigned long long a00 = binit0, a01 = binit1, a10 = binit0, a11 = binit1;

        float stg[4];
        // prologue: stage k-block 0
        {
#pragma unroll
            for (int p = 0; p < 4; p++) {
                int idx = tid + p * NTHR;
                int r = idx >> 5, kl = idx & 31;
                stg[p] = __ldcg(&g_h[(b0 + r) * HH + kl]);
            }
#pragma unroll
            for (int p = 0; p < 4; p++) {
                int idx = tid + p * NTHR;
                int r = idx >> 5, kl = idx & 31;
                hsA[kl * 34 + r] = stg[p];
            }
        }
        __syncthreads();

#pragma unroll 1
        for (int kb = 0; kb < 11; kb++) {
            // prefetch next k-block (overlaps with FMA below)
            if (kb < 10) {
                int kn = kb + 1;
#pragma unroll
                for (int p = 0; p < 4; p++) {
                    int idx = tid + p * NTHR;
                    int r = idx >> 5, kl = idx & 31;
                    int b = b0 + r;
                    if (kn < 8)       stg[p] = __ldcg(&g_h[b * HH + kn * 32 + kl]);
                    else if (kn < 10) stg[p] = signal[(b * TT + t) * SIG + (kn - 8) * 32 + kl];
                    else              stg[p] = metmast[(b * TT + t) * MET + kl];
                }
            }
            const float* hb = &hsA[(kb & 1) * 1088];
            const float* ub = &U_s[kb * 32 * 64];
#pragma unroll
            for (int kl = 0; kl < 32; kl++) {
                float2 h2 = *(const float2*)&hb[kl * 34 + ty * 2];
                unsigned long long h00 = pack2(h2.x, h2.x);
                unsigned long long h11 = pack2(h2.y, h2.y);
                ulonglong2 uu = *(const ulonglong2*)&ub[kl * 64 + tx * 4];
                fma2(a00, h00, uu.x); fma2(a01, h00, uu.y);
                fma2(a10, h11, uu.x); fma2(a11, h11, uu.y);
            }
            if (kb < 10) {
                float* hn = &hsA[((kb + 1) & 1) * 1088];
#pragma unroll
                for (int p = 0; p < 4; p++) {
                    int idx = tid + p * NTHR;
                    int r = idx >> 5, kl = idx & 31;
                    hn[kl * 34 + r] = stg[p];
                }
                __syncthreads();
            }
        }
        // publish Z tile to L2 (consumed only by this group's CTAs)
        {
            int r = b0 + ty * 2;
            unsigned long long* p0 = (unsigned long long*)&g_Z[r * NG + c0 + tx * 4];
            unsigned long long* p1 = (unsigned long long*)&g_Z[(r + 1) * NG + c0 + tx * 4];
            asm volatile("st.global.cg.v2.u64 [%0], {%1, %2};" :: "l"(p0), "l"(a00), "l"(a01) : "memory");
            asm volatile("st.global.cg.v2.u64 [%0], {%1, %2};" :: "l"(p1), "l"(a10), "l"(a11) : "memory");
        }
        group_barrier(bt, ++gen);

        // ================= elementwise phase (own 2 rows, state in smem) ============
        if (tid < BPC * 96) {
            int lb = tid / 96, j = tid - lb * 96;
            int b = bown0 + lb;
            x_s[tid] = (j < SIG) ? signal[(b * TT + t) * SIG + j]
                                 : metmast[(b * TT + t) * MET + (j - SIG)];
        }
        __syncthreads();

        const float* tc = &trig_a[t * 32];

#pragma unroll 1
        for (int lb = 0; lb < BPC; lb++) {
            int b = bown0 + lb;
            // fre gate: hsig(bfre + [h|xs|xm] . Ufre)
            {
                int f = tid & 15, ch = tid >> 4;
                float s = 0.f;
                int k0 = ch * 22;   // 16 chunks * 22 = 352
#pragma unroll
                for (int q = 0; q < 22; q++) {
                    int k = k0 + q;
                    float av = (k < HH) ? h_s[lb * HH + k] : x_s[lb * 96 + (k - HH)];
                    s = fmaf(av, Ufre_s[k * FF + f], s);
                }
                red[tid] = s;
                __syncthreads();
                if (tid < FF) {
                    float tot = g_bfre[tid];
#pragma unroll
                    for (int j = 0; j < 16; j++) tot += red[tid + 16 * j];
                    fre_s[lb * FF + tid] = hsig(tot);
                }
                __syncthreads();
            }
            const float* Zb = &g_Z[b * NG];
            float xi   = __ldcg(&Zb[tid]);
            float xste = __ldcg(&Zb[HH + tid]);
            float xc   = __ldcg(&Zb[2 * HH + tid]);
            float xo   = __ldcg(&Zb[3 * HH + tid]);
            float ig  = hsig(xi);
            float ste = hsig(xste);
            float cg  = ig * tanhf(xc);
            float og  = hsig(xo);
            float acc_a = 0.f;
#pragma unroll
            for (int f = 0; f < FF; f++) {
                float fm = ste * fre_s[lb * FF + f];
                int sidx = (lb * FF + f) * HH + tid;
                float sr = fmaf(fm, S_re[sidx], cg * tc[f]);
                float si = fmaf(fm, S_im[sidx], cg * tc[16 + f]);
                S_re[sidx] = sr; S_im[sidx] = si;
                acc_a = fmaf(fmaf(sr, sr, si * si), ua_r[f], acc_a);
            }
            float a  = tanhf(acc_a + ba_r);
            float hn = og * a;
            h_s[lb * HH + tid] = hn;
            __stcg(&g_h[b * HH + tid], hn);
        }
        group_barrier(bt, ++gen);
    }

    // ================= output: out[b] = ((h.Wp + bp) * fcw + fcb) =================
    for (int lb = 0; lb < BPC; lb++) {
        int b = bown0 + lb;
        red[tid] = h_s[lb * HH + tid] * Wp[tid];
        __syncthreads();
        for (int s = 128; s > 0; s >>= 1) {
            if (tid < s) red[tid] += red[tid + s];
            __syncthreads();
        }
        if (tid == 0) out[b] = fmaf(red[0] + bp[0], fcw[0], fcb[0]);
        __syncthreads();
    }
}

// ---------------- launch ----------------
extern "C" void kernel_launch(void* const* d_in, const int* in_sizes, int n_in,
                              void* d_out, int out_size) {
    const float* signal = (const float*)d_in[0];
    const float* metmast = (const float*)d_in[1];
    const float* Wi_s   = (const float*)d_in[2];
    const float* Wste_s = (const float*)d_in[3];
    const float* Wfre_s = (const float*)d_in[4];
    const float* Wc_s   = (const float*)d_in[5];
    const float* Wo_s   = (const float*)d_in[6];
    const float* Wi_m   = (const float*)d_in[7];
    const float* Wste_m = (const float*)d_in[8];
    const float* Wfre_m = (const float*)d_in[9];
    const float* Wc_m   = (const float*)d_in[10];
    const float* Wo_m   = (const float*)d_in[11];
    const float* Ui     = (const float*)d_in[12];
    const float* bi     = (const float*)d_in[13];
    const float* Uste   = (const float*)d_in[14];
    const float* bste   = (const float*)d_in[15];
    const float* Ufre   = (const float*)d_in[16];
    const float* bfre   = (const float*)d_in[17];
    const float* Uc     = (const float*)d_in[18];
    const float* bc     = (const float*)d_in[19];
    const float* Uo     = (const float*)d_in[20];
    const float* bo     = (const float*)d_in[21];
    const float* Ua     = (const float*)d_in[22];
    const float* ba     = (const float*)d_in[23];
    const float* Wp     = (const float*)d_in[24];
    const float* bp     = (const float*)d_in[25];
    const float* fcw    = (const float*)d_in[26];
    const float* fcb    = (const float*)d_in[27];
    float* out = (float*)d_out;

    static int smem_set = 0;
    const int SMEM_BYTES = SM_TOTAL * 4;   // 207488 B
    if (!smem_set) {
        cudaFuncSetAttribute(sfm_kernel, cudaFuncAttributeMaxDynamicSharedMemorySize, SMEM_BYTES);
        smem_set = 1;
    }

    pack_kernel<<<64, 256>>>(Wi_s, Wste_s, Wfre_s, Wc_s, Wo_s,
                             Wi_m, Wste_m, Wfre_m, Wc_m, Wo_m,
                             Ui, bi, Uste, bste, Ufre, bfre, Uc, bc, Uo, bo);
    sfm_kernel<<<NCTA, NTHR, SMEM_BYTES>>>(signal, metmast, Ua, ba, Wp, bp, fcw, fcb, out);
}

// round 10
// speedup vs baseline: 1.6051x; 1.1831x over previous
#include <cuda_runtime.h>

#define TT   128
#define BB   256
#define SIG  64
#define MET  32
#define HH   256
#define FF   16
#define KTOT 352          // 256 (h) + 64 (signal) + 32 (metmast)
#define NCOL 80           // per-CTA cols: 4 gates x 16 hidden + 16 fre
#define NG2  1280         // 16 ctiles * 80
#define NCTA 128
#define NTHR 256
#define NGRP 16           // CTAs per barrier group (one b-tile)

// ---------------- scratch (static device allocations only) ----------------
__device__ __align__(16) float g_Upk[KTOT * NG2];   // packed per-ctile [i|ste|c|o (16 each) | fre(16)]
__device__ __align__(16) float g_bias2[NG2];
__device__ __align__(16) float g_trig[TT * 32];     // per step: 16 cos then 16 sin
__device__ __align__(16) float g_h[2 * BB * HH];    // double-buffered hidden state
__device__ __align__(256) unsigned g_gbar[8 * 64];  // [grp*64+0]=count, [grp*64+1]=gen

// ---------------- helpers ----------------
__device__ __forceinline__ float hsig(float x) {
    return __saturatef(fmaf(x, 0.16666667f, 0.5f));
}
__device__ __forceinline__ unsigned long long pack2(float x, float y) {
    unsigned long long r;
    asm("mov.b64 %0, {%1, %2};" : "=l"(r) : "f"(x), "f"(y));
    return r;
}
__device__ __forceinline__ void unpack2(float &x, float &y, unsigned long long v) {
    asm("mov.b64 {%0, %1}, %2;" : "=f"(x), "=f"(y) : "l"(v));
}
__device__ __forceinline__ void fma2(unsigned long long &d, unsigned long long a, unsigned long long b) {
    asm("fma.rn.f32x2 %0, %1, %2, %0;" : "+l"(d) : "l"(a), "l"(b));
}

// 16-CTA group barrier, release/acquire through L2 only (cross-CTA data uses
// __ldcg/__stcg, so L1 never needs invalidation).
__device__ __forceinline__ void group_barrier(int grp, unsigned gen) {
    __syncthreads();
    if (threadIdx.x == 0) {
        unsigned* cnt = &g_gbar[grp * 64];
        unsigned* gv  = &g_gbar[grp * 64 + 1];
        unsigned arr;
        asm volatile("atom.add.acq_rel.gpu.global.u32 %0, [%1], 1;"
                     : "=r"(arr) : "l"(cnt) : "memory");
        if (arr == NGRP - 1) {
            asm volatile("st.relaxed.gpu.global.u32 [%0], 0;" :: "l"(cnt) : "memory");
            asm volatile("st.release.gpu.global.u32 [%0], %1;" :: "l"(gv), "r"(gen) : "memory");
        } else {
            unsigned cur;
            do {
                asm volatile("ld.acquire.gpu.global.u32 %0, [%1];"
                             : "=r"(cur) : "l"(gv) : "memory");
            } while (cur < gen);
        }
    }
    __syncthreads();
}

// ---------------- pack kernel ----------------
__global__ void pack_kernel(
    const float* __restrict__ Wi_s,  const float* __restrict__ Wste_s, const float* __restrict__ Wfre_s,
    const float* __restrict__ Wc_s,  const float* __restrict__ Wo_s,
    const float* __restrict__ Wi_m,  const float* __restrict__ Wste_m, const float* __restrict__ Wfre_m,
    const float* __restrict__ Wc_m,  const float* __restrict__ Wo_m,
    const float* __restrict__ Ui,    const float* __restrict__ bi,
    const float* __restrict__ Uste,  const float* __restrict__ bste,
    const float* __restrict__ Ufre,  const float* __restrict__ bfre,
    const float* __restrict__ Uc,    const float* __restrict__ bc,
    const float* __restrict__ Uo,    const float* __restrict__ bo)
{
    int idx0   = blockIdx.x * blockDim.x + threadIdx.x;
    int stride = gridDim.x * blockDim.x;

    for (int idx = idx0; idx < KTOT * NG2; idx += stride) {
        int k = idx / NG2, c2 = idx - k * NG2;
        int ctile = c2 / NCOL, c = c2 - ctile * NCOL;
        float v;
        if (c < 64) {
            int g = c >> 4, j = ctile * 16 + (c & 15);
            const float* U4[4]  = {Ui, Uste, Uc, Uo};
            const float* Ws4[4] = {Wi_s, Wste_s, Wc_s, Wo_s};
            const float* Wm4[4] = {Wi_m, Wste_m, Wc_m, Wo_m};
            if (k < HH)            v = U4[g][k * HH + j];
            else if (k < HH + SIG) v = Ws4[g][(k - HH) * HH + j];
            else                   v = Wm4[g][(k - HH - SIG) * HH + j];
        } else {
            int f = c - 64;
            if (k < HH)            v = Ufre[k * FF + f];
            else if (k < HH + SIG) v = Wfre_s[(k - HH) * FF + f];
            else                   v = Wfre_m[(k - HH - SIG) * FF + f];
        }
        g_Upk[idx] = v;
    }
    for (int idx = idx0; idx < NG2; idx += stride) {
        int ctile = idx / NCOL, c = idx - ctile * NCOL;
        float v;
        if (c < 64) {
            int g = c >> 4, j = ctile * 16 + (c & 15);
            const float* b4[4] = {bi, bste, bc, bo};
            v = b4[g][j];
        } else {
            v = bfre[c - 64];
        }
        g_bias2[idx] = v;
    }
    for (int idx = idx0; idx < TT * FF; idx += stride) {
        int t = idx / FF, f = idx % FF;
        float om = 6.2831854820251465f * (float)(t + 1) * ((float)f / 16.0f);
        double omd = (double)om;
        g_trig[t * 32 + f]      = (float)cos(omd);
        g_trig[t * 32 + 16 + f] = (float)sin(omd);
    }
    for (int idx = idx0; idx < 8 * 64; idx += stride) g_gbar[idx] = 0;
}

// ---------------- persistent recurrent kernel ----------------
// SMEM layout (float offsets):
#define SM_US    0                          // 352*80 = 28160 (weight slice, persistent)
#define SM_S     (SM_US + KTOT * NCOL)      // S as float2[(f*512 + r*16 + j)]: 16384 floats
#define SM_A     (SM_S  + 16384)            // double-buffered A tile: 2*32*34 = 2176
#define SM_Z     (SM_A  + 2176)             // Zs[32][80] = 2560
#define SM_TRIG  (SM_Z  + 2560)             // 32
#define SM_TOTAL (SM_TRIG + 32)             // 49312 floats = 197248 B

__global__ void __launch_bounds__(NTHR, 1) sfm_kernel(
    const float* __restrict__ signal, const float* __restrict__ metmast,
    const float* __restrict__ Ua,     const float* __restrict__ ba,
    const float* __restrict__ Wp,     const float* __restrict__ bp,
    const float* __restrict__ fcw,    const float* __restrict__ fcb,
    float* __restrict__ out)
{
    extern __shared__ float sm[];
    float*  U_s    = sm + SM_US;
    float2* Sp     = (float2*)(sm + SM_S);
    float*  hsA    = sm + SM_A;
    float*  Zs     = sm + SM_Z;
    float*  trig_s = sm + SM_TRIG;

    const int tid   = threadIdx.x;
    const int ct    = blockIdx.x;
    const int bt    = ct & 7;            // b-tile of 32 rows == barrier group
    const int ctile = ct >> 3;           // 16-hidden slice index
    const int b0    = bt * 32;
    const int ty    = tid >> 4;          // GEMM rows ty*2, ty*2+1
    const int tx    = tid & 15;          // GEMM cols tx*4 .. +4 (and fre col tx)

    // elementwise ownership: thread -> row pr, hidden pair pj, pj+1 (local)
    const int pr = tid >> 3;
    const int pj = (tid & 7) * 2;
    const int jg = ctile * 16 + pj;      // global hidden index

    // ---- persistent weight slice into smem ----
    for (int idx = tid; idx < KTOT * NCOL; idx += NTHR) {
        int k = idx / NCOL, c = idx - k * NCOL;
        U_s[idx] = g_Upk[k * NG2 + ctile * NCOL + c];
    }
    // ---- state init ----
    for (int i = tid; i < 8192; i += NTHR) Sp[i] = make_float2(0.f, 0.f);
    for (int i = tid; i < 512; i += NTHR) {          // own (r, j) slice, both buffers
        int r = i >> 4, j = i & 15;
        int off = (b0 + r) * HH + ctile * 16 + j;
        __stcg(&g_h[off], 0.f);
        __stcg(&g_h[BB * HH + off], 0.f);
    }

    float ba0 = ba[jg], ba1 = ba[jg + 1];
    float ua_r[FF];
#pragma unroll
    for (int f = 0; f < FF; f++) ua_r[f] = Ua[f];

    // accumulator bias init (constant across steps)
    unsigned long long binit0, binit1, binitf;
    {
        float4 bv = *(const float4*)&g_bias2[ctile * NCOL + tx * 4];
        binit0 = pack2(bv.x, bv.y); binit1 = pack2(bv.z, bv.w);
        float bf = g_bias2[ctile * NCOL + 64 + tx];
        binitf = pack2(bf, bf);
    }

    unsigned gen = 0;
    group_barrier(bt, ++gen);

    for (int t = 0; t < TT; t++) {
        const float* hprev = g_h + ((t + 1) & 1) * BB * HH;   // h(t-1)
        float*       hcur  = g_h + (t & 1) * BB * HH;         // h(t)

        // ---- prologue: stage k-block 0 (h rows) ----
        float stg[4];
        {
#pragma unroll
            for (int p = 0; p < 4; p++) {
                int idx = tid + p * NTHR;
                int r = idx >> 5, kl = idx & 31;
                stg[p] = __ldcg(&hprev[(b0 + r) * HH + kl]);
            }
#pragma unroll
            for (int p = 0; p < 4; p++) {
                int idx = tid + p * NTHR;
                int r = idx >> 5, kl = idx & 31;
                hsA[kl * 34 + r] = stg[p];
            }
        }
        if (tid < 32) trig_s[tid] = g_trig[t * 32 + tid];
        __syncthreads();

        // ---- GEMM: Z[32 x 80] = bias + A[32 x 352] @ U_s[352 x 80] ----
        unsigned long long a00 = binit0, a01 = binit1, a10 = binit0, a11 = binit1;
        unsigned long long accf = binitf;

#pragma unroll 1
        for (int kb = 0; kb < 11; kb++) {
            if (kb < 10) {
                int kn = kb + 1;
#pragma unroll
                for (int p = 0; p < 4; p++) {
                    int idx = tid + p * NTHR;
                    int r = idx >> 5, kl = idx & 31;
                    int b = b0 + r;
                    if (kn < 8)       stg[p] = __ldcg(&hprev[b * HH + kn * 32 + kl]);
                    else if (kn < 10) stg[p] = signal[(b * TT + t) * SIG + (kn - 8) * 32 + kl];
                    else              stg[p] = metmast[(b * TT + t) * MET + kl];
                }
            }
            const float* hb = &hsA[(kb & 1) * 1088];
            const float* ub = &U_s[kb * 32 * NCOL];
#pragma unroll
            for (int kl = 0; kl < 32; kl++) {
                float2 h2 = *(const float2*)&hb[kl * 34 + ty * 2];
                ulonglong2 uu = *(const ulonglong2*)&ub[kl * NCOL + tx * 4];
                float w = ub[kl * NCOL + 64 + tx];
                unsigned long long h00 = pack2(h2.x, h2.x);
                unsigned long long h11 = pack2(h2.y, h2.y);
                unsigned long long hp  = pack2(h2.x, h2.y);
                unsigned long long wp  = pack2(w, w);
                fma2(a00, h00, uu.x); fma2(a01, h00, uu.y);
                fma2(a10, h11, uu.x); fma2(a11, h11, uu.y);
                fma2(accf, hp, wp);
            }
            if (kb < 10) {
                float* hn = &hsA[((kb + 1) & 1) * 1088];
#pragma unroll
                for (int p = 0; p < 4; p++) {
                    int idx = tid + p * NTHR;
                    int r = idx >> 5, kl = idx & 31;
                    hn[kl * 34 + r] = stg[p];
                }
                __syncthreads();
            }
        }
        // ---- Z tile to shared (never leaves the CTA) ----
        {
            int r = ty * 2;
            *(unsigned long long*)&Zs[r * NCOL + tx * 4]           = a00;
            *(unsigned long long*)&Zs[r * NCOL + tx * 4 + 2]       = a01;
            *(unsigned long long*)&Zs[(r + 1) * NCOL + tx * 4]     = a10;
            *(unsigned long long*)&Zs[(r + 1) * NCOL + tx * 4 + 2] = a11;
            float f0, f1; unpack2(f0, f1, accf);
            Zs[r * NCOL + 64 + tx]       = f0;     // fre pre-act, row r
            Zs[(r + 1) * NCOL + 64 + tx] = f1;     // row r+1
        }
        __syncthreads();

        // ---- elementwise: fully CTA-local (row pr, hidden pj/pj+1) ----
        {
            const float* Zr = &Zs[pr * NCOL];
            float ig0  = hsig(Zr[pj]),       ig1  = hsig(Zr[pj + 1]);
            float ste0 = hsig(Zr[16 + pj]),  ste1 = hsig(Zr[16 + pj + 1]);
            float cg0  = ig0 * tanhf(Zr[32 + pj]);
            float cg1  = ig1 * tanhf(Zr[32 + pj + 1]);
            float og0  = hsig(Zr[48 + pj]),  og1 = hsig(Zr[48 + pj + 1]);
            float acc0 = 0.f, acc1 = 0.f;
#pragma unroll
            for (int f = 0; f < FF; f++) {
                float fre = hsig(Zr[64 + f]);
                float cs = trig_s[f], sn = trig_s[16 + f];
                float fm0 = ste0 * fre, fm1 = ste1 * fre;
                int sidx = f * 512 + pr * 16 + pj;
                float2 s0 = Sp[sidx], s1 = Sp[sidx + 1];
                float sr0 = fmaf(fm0, s0.x, cg0 * cs);
                float si0 = fmaf(fm0, s0.y, cg0 * sn);
                float sr1 = fmaf(fm1, s1.x, cg1 * cs);
                float si1 = fmaf(fm1, s1.y, cg1 * sn);
                Sp[sidx]     = make_float2(sr0, si0);
                Sp[sidx + 1] = make_float2(sr1, si1);
                acc0 = fmaf(fmaf(sr0, sr0, si0 * si0), ua_r[f], acc0);
                acc1 = fmaf(fmaf(sr1, sr1, si1 * si1), ua_r[f], acc1);
            }
            float a0 = tanhf(acc0 + ba0), a1 = tanhf(acc1 + ba1);
            int off = (b0 + pr) * HH + jg;
            __stcg(&hcur[off],     og0 * a0);
            __stcg(&hcur[off + 1], og1 * a1);
        }
        group_barrier(bt, ++gen);
    }

    // ---- output: 8 CTAs (ctile==0) compute out for their 32 rows ----
    if (ct < 8) {
        const float* hf = g_h + ((TT - 1) & 1) * BB * HH;
        int r   = tid >> 3;          // 0..31
        int seg = tid & 7;           // 8 segments of 32 hidden
        const float* hr = &hf[(ct * 32 + r) * HH + seg * 32];
        const float* wq = &Wp[seg * 32];
        float s = 0.f;
#pragma unroll
        for (int q = 0; q < 32; q++) s = fmaf(__ldcg(&hr[q]), wq[q], s);
        s += __shfl_down_sync(0xffffffffu, s, 4);
        s += __shfl_down_sync(0xffffffffu, s, 2);
        s += __shfl_down_sync(0xffffffffu, s, 1);
        if ((tid & 7) == 0) out[ct * 32 + r] = fmaf(s + bp[0], fcw[0], fcb[0]);
    }
}

// ---------------- launch ----------------
extern "C" void kernel_launch(void* const* d_in, const int* in_sizes, int n_in,
                              void* d_out, int out_size) {
    const float* signal = (const float*)d_in[0];
    const float* metmast = (const float*)d_in[1];
    const float* Wi_s   = (const float*)d_in[2];
    const float* Wste_s = (const float*)d_in[3];
    const float* Wfre_s = (const float*)d_in[4];
    const float* Wc_s   = (const float*)d_in[5];
    const float* Wo_s   = (const float*)d_in[6];
    const float* Wi_m   = (const float*)d_in[7];
    const float* Wste_m = (const float*)d_in[8];
    const float* Wfre_m = (const float*)d_in[9];
    const float* Wc_m   = (const float*)d_in[10];
    const float* Wo_m   = (const float*)d_in[11];
    const float* Ui     = (const float*)d_in[12];
    const float* bi     = (const float*)d_in[13];
    const float* Uste   = (const float*)d_in[14];
    const float* bste   = (const float*)d_in[15];
    const float* Ufre   = (const float*)d_in[16];
    const float* bfre   = (const float*)d_in[17];
    const float* Uc     = (const float*)d_in[18];
    const float* bc     = (const float*)d_in[19];
    const float* Uo     = (const float*)d_in[20];
    const float* bo     = (const float*)d_in[21];
    const float* Ua     = (const float*)d_in[22];
    const float* ba     = (const float*)d_in[23];
    const float* Wp     = (const float*)d_in[24];
    const float* bp     = (const float*)d_in[25];
    const float* fcw    = (const float*)d_in[26];
    const float* fcb    = (const float*)d_in[27];
    float* out = (float*)d_out;

    static int smem_set = 0;
    const int SMEM_BYTES = SM_TOTAL * 4;   // 197248 B
    if (!smem_set) {
        cudaFuncSetAttribute(sfm_kernel, cudaFuncAttributeMaxDynamicSharedMemorySize, SMEM_BYTES);
        smem_set = 1;
    }

    pack_kernel<<<64, 256>>>(Wi_s, Wste_s, Wfre_s, Wc_s, Wo_s,
                             Wi_m, Wste_m, Wfre_m, Wc_m, Wo_m,
                             Ui, bi, Uste, bste, Ufre, bfre, Uc, bc, Uo, bo);
    sfm_kernel<<<NCTA, NTHR, SMEM_BYTES>>>(signal, metmast, Ua, ba, Wp, bp, fcw, fcb, out);
}